// round 15
// baseline (speedup 1.0000x reference)
#include <cuda_runtime.h>
#include <cuda_fp16.h>
#include <cstdint>
#include <cstddef>

#define NHEADS   8
#define MEMDIM   1024
#define MEMSIZE  32768
#define TZ       128
#define NCTA     148

// smem: stage b at base + b*65536 (K at +0, V at +32768); Q (256 rows) at +131072
#define STAGE_BYTES 65536u
#define OFF_Q       131072u
#define SMEM_BYTES  196608u            // 192 KB

// fp16 copies of the inputs (filled by prepass each launch)
// g_Qh holds Q pre-scaled by log2(e) so exp(S) = ex2(S')
__device__ __half g_Qh[1024 * 1024];
__device__ __half g_Kh[(size_t)MEMSIZE * MEMDIM];
__device__ __half g_Vh[(size_t)MEMDIM * MEMSIZE];

// per-(CTA,segment) partial outputs: 256 rows x 128 d
__device__ float g_Opart[(size_t)2 * NCTA * 256 * 128];
__device__ float g_Rpart[2 * NCTA * 256];

// static partition of 8192 = 52*56 + 96*55
__host__ __device__ __forceinline__ int cta_start2(int i) {
    return i * 55 + (i < 52 ? i : 52);
}
__host__ __device__ __forceinline__ int cta_len2(int i) {
    return 55 + (i < 52 ? 1 : 0);
}

// ---------------- helpers ----------------
__device__ __forceinline__ uint32_t smem_u32(const void* p) {
    uint32_t a;
    asm("{ .reg .u64 t; cvta.to.shared.u64 t, %1; cvt.u32.u64 %0, t; }" : "=r"(a) : "l"(p));
    return a;
}

#define CP16(dst, src) \
    asm volatile("cp.async.cg.shared.global [%0], [%1], 16;" :: "r"(dst), "l"(src) : "memory")
#define CP_COMMIT() asm volatile("cp.async.commit_group;" ::: "memory")
#define CP_WAIT(n)  asm volatile("cp.async.wait_group %0;" :: "n"(n) : "memory")

#define LDSM4(r0, r1, r2, r3, a) \
    asm volatile("ldmatrix.sync.aligned.m8n8.x4.shared.b16 {%0,%1,%2,%3}, [%4];" \
        : "=r"(r0), "=r"(r1), "=r"(r2), "=r"(r3) : "r"(a))

#define MMAH(c, a0, a1, a2, a3, b0, b1) \
    asm volatile("mma.sync.aligned.m16n8k16.row.col.f32.f16.f16.f32 " \
        "{%0,%1,%2,%3}, {%4,%5,%6,%7}, {%8,%9}, {%0,%1,%2,%3};" \
        : "+f"((c)[0]), "+f"((c)[1]), "+f"((c)[2]), "+f"((c)[3]) \
        : "r"(a0), "r"(a1), "r"(a2), "r"(a3), "r"(b0), "r"(b1))

__device__ __forceinline__ uint32_t packh2(float lo, float hi) {
    __half2 h = __floats2half2_rn(lo, hi);
    return *reinterpret_cast<uint32_t*>(&h);
}

// exp2 of a packed f16x2 (one MUFU op for two values)
__device__ __forceinline__ uint32_t ex2h2(uint32_t p) {
    uint32_t r;
    asm("ex2.approx.f16x2 %0, %1;" : "=r"(r) : "r"(p));
    return r;
}

// exp (base-2, pre-scaled) of one 4-reg score block -> two half2 frags; f32 row sums
__device__ __forceinline__ void exp_block(const float* s, uint32_t& lo, uint32_t& hi,
                                          float& r0, float& r1) {
    lo = ex2h2(packh2(s[0], s[1]));
    hi = ex2h2(packh2(s[2], s[3]));
    float2 el = __half22float2(*reinterpret_cast<const __half2*>(&lo));
    float2 eh = __half22float2(*reinterpret_cast<const __half2*>(&hi));
    r0 += el.x + el.y;
    r1 += eh.x + eh.y;
}

// ============================================================
// prepass: f32 -> fp16 copies; Q scaled by log2(e)
// ============================================================
__global__ void __launch_bounds__(256)
kvmem_prepass(const float* __restrict__ hin, const float* __restrict__ keys,
              const float* __restrict__ values) {
    const size_t NQ4 = (size_t)1024 * 1024 / 4;
    const size_t NK4 = (size_t)MEMSIZE * MEMDIM / 4;
    const size_t NV4 = NK4;
    const size_t TOT = NQ4 + NK4 + NV4;
    const float LOG2E = 1.4426950408889634f;
    size_t stride = (size_t)gridDim.x * blockDim.x;
    for (size_t i = (size_t)blockIdx.x * blockDim.x + threadIdx.x; i < TOT; i += stride) {
        const float4* src;
        uint2* dst;
        size_t off;
        float scale;
        if (i < NQ4) {
            src = (const float4*)hin; dst = (uint2*)g_Qh; off = i; scale = LOG2E;
        } else if (i < NQ4 + NK4) {
            src = (const float4*)keys; dst = (uint2*)g_Kh; off = i - NQ4; scale = 1.0f;
        } else {
            src = (const float4*)values; dst = (uint2*)g_Vh; off = i - NQ4 - NK4; scale = 1.0f;
        }
        float4 v = src[off];
        uint2 u;
        u.x = packh2(v.x * scale, v.y * scale);
        u.y = packh2(v.z * scale, v.w * scale);
        dst[off] = u;
    }
}

// ============================================================
// main: 148 CTAs x 256 threads; one work item = (head, mtile-pair, chunk);
// warp w owns m rows [32w, 32w+32) of the CTA's 256 query rows
// ============================================================
__global__ void __launch_bounds__(256, 1)
kvmem_main() {
    extern __shared__ __align__(1024) char dsm[];
    const uint32_t base = smem_u32(dsm);

    const int tid  = threadIdx.x;
    const int lane = tid & 31;
    const int w    = tid >> 5;
    const int ci   = blockIdx.x;

    const int rstart = cta_start2(ci);
    const int rend   = rstart + cta_len2(ci);

    const uint32_t Kb[2] = { base, base + STAGE_BYTES };
    const uint32_t Qs    = base + OFF_Q;

    // per-thread precomputed K/V load offsets (128 rows x 16 16B-chunks)
    uint32_t tdoff[8], ksoff[8], vsoff[8];
#pragma unroll
    for (int n = 0; n < 8; n++) {
        int c = tid + 256 * n;
        int r = c >> 4, ch = c & 15;
        tdoff[n] = (uint32_t)(r * 256 + ((ch ^ (r & 7)) << 4));
        ksoff[n] = (uint32_t)(((size_t)r * MEMDIM + ch * 8) * 2);
        vsoff[n] = (uint32_t)(((size_t)r * MEMSIZE + ch * 8) * 2);
    }

    // lane addressing constants
    const int arow_off = ((lane >> 3) & 1) * 8 + (lane & 7);   // A-frag x4 pattern
    const int ach_off  = lane >> 4;
    const int krow_off = ((lane >> 4) << 3) + (lane & 7);      // B-frag x4 pattern
    const int kch_off  = (lane >> 3) & 1;
    const int qrow0 = w * 32 + arow_off;
    const int qrow1 = qrow0 + 16;

    int seg = 0;
    int g = rstart;
    while (g < rend) {
        const int hm2    = g >> 8;
        const int segend = min(rend, (hm2 + 1) << 8);
        const int n      = segend - g;
        const int c0     = g & 255;
        const int head   = hm2 >> 2, mtp = hm2 & 3;

        const char* kptr = (const char*)(g_Kh + head * 128);
        const char* vptr = (const char*)(g_Vh + (size_t)(head * 128) * MEMSIZE);

        auto loadKV = [&](int c, int b) {
            const char* ks = kptr + (size_t)c * (TZ * MEMDIM * 2);
            const char* vs = vptr + (size_t)c * (TZ * 2);
#pragma unroll
            for (int q = 0; q < 8; q++) CP16(Kb[b] + tdoff[q], ks + ksoff[q]);
#pragma unroll
            for (int q = 0; q < 8; q++) CP16(Kb[b] + 32768u + tdoff[q], vs + vsoff[q]);
        };

        // ---------- stage Q: 256 rows x 256B, swizzled ----------
        {
            const __half* qsrc = g_Qh + (size_t)(mtp * 256) * MEMDIM + head * 128;
#pragma unroll
            for (int c = tid; c < 4096; c += 256) {
                int m = c >> 4, ch = c & 15;
                uint32_t dst = Qs + m * 256 + (uint32_t)((ch ^ (m & 7)) << 4);
                CP16(dst, qsrc + (size_t)m * MEMDIM + ch * 8);
            }
            CP_COMMIT();
        }
        loadKV(c0, 0); CP_COMMIT();
        if (n > 1) loadKV(c0 + 1, 1);
        CP_COMMIT();

        CP_WAIT(2);
        __syncthreads();

        // O^T accumulators: [u: d16-tile][nb = 2mt+h: n8-block of warp's 32 rows][4]
        float oc[8][4][4];
#pragma unroll
        for (int u = 0; u < 8; u++)
#pragma unroll
            for (int nb = 0; nb < 4; nb++) { oc[u][nb][0] = oc[u][nb][1] = oc[u][nb][2] = oc[u][nb][3] = 0.f; }
        float rs[4] = {0.f, 0.f, 0.f, 0.f};

#pragma unroll 1
        for (int j = 0; j < n; j++) {
            const int b = j & 1;
            CP_WAIT(1);
            __syncthreads();
            const uint32_t kb = Kb[b], vb = Kb[b] + 32768u;

#pragma unroll
            for (int zc = 0; zc < 4; zc++) {     // 32-z sub-chunks
                // ---------- GEMM1: S[32m x 32z] ----------
                float sc[2][4][4];
#pragma unroll
                for (int m2 = 0; m2 < 2; m2++)
#pragma unroll
                    for (int blk = 0; blk < 4; blk++) { sc[m2][blk][0] = sc[m2][blk][1] = sc[m2][blk][2] = sc[m2][blk][3] = 0.f; }

#pragma unroll
                for (int s = 0; s < 8; s++) {
                    uint32_t qa0[4], qa1[4];
                    {
                        int ch = 2 * s + ach_off;
                        uint32_t a0 = Qs + qrow0 * 256 + (uint32_t)((ch ^ (qrow0 & 7)) << 4);
                        uint32_t a1 = Qs + qrow1 * 256 + (uint32_t)((ch ^ (qrow1 & 7)) << 4);
                        LDSM4(qa0[0], qa0[1], qa0[2], qa0[3], a0);
                        LDSM4(qa1[0], qa1[1], qa1[2], qa1[3], a1);
                    }
#pragma unroll
                    for (int kk = 0; kk < 2; kk++) {
                        int row = 32 * zc + 16 * kk + krow_off;
                        int ch  = 2 * s + kch_off;
                        uint32_t a = kb + row * 256 + (uint32_t)((ch ^ (row & 7)) << 4);
                        uint32_t r0, r1, r2, r3;
                        LDSM4(r0, r1, r2, r3, a);
                        MMAH(sc[0][2 * kk],     qa0[0], qa0[1], qa0[2], qa0[3], r0, r1);
                        MMAH(sc[0][2 * kk + 1], qa0[0], qa0[1], qa0[2], qa0[3], r2, r3);
                        MMAH(sc[1][2 * kk],     qa1[0], qa1[1], qa1[2], qa1[3], r0, r1);
                        MMAH(sc[1][2 * kk + 1], qa1[0], qa1[1], qa1[2], qa1[3], r2, r3);
                    }
                }

                // ---------- exp (pipelined, fp16) + GEMM2: O^T += V . P^T ----------
                uint32_t cur[2][4], nxt[2][4];
                exp_block(sc[0][0], cur[0][0], cur[0][2], rs[0], rs[1]);
                exp_block(sc[0][1], cur[0][1], cur[0][3], rs[0], rs[1]);
                exp_block(sc[1][0], cur[1][0], cur[1][2], rs[2], rs[3]);
                exp_block(sc[1][1], cur[1][1], cur[1][3], rs[2], rs[3]);
#pragma unroll
                for (int ks = 0; ks < 2; ks++) {
                    if (ks == 0) {
                        exp_block(sc[0][2], nxt[0][0], nxt[0][2], rs[0], rs[1]);
                        exp_block(sc[0][3], nxt[0][1], nxt[0][3], rs[0], rs[1]);
                        exp_block(sc[1][2], nxt[1][0], nxt[1][2], rs[2], rs[3]);
                        exp_block(sc[1][3], nxt[1][1], nxt[1][3], rs[2], rs[3]);
                    }
#pragma unroll
                    for (int u = 0; u < 8; u++) {
                        int row = 16 * u + arow_off;
                        int ch  = 4 * zc + 2 * ks + ach_off;
                        uint32_t a = vb + row * 256 + (uint32_t)((ch ^ (row & 7)) << 4);
                        uint32_t a0, a1, a2, a3;
                        LDSM4(a0, a1, a2, a3, a);
                        MMAH(oc[u][0], a0, a1, a2, a3, cur[0][0], cur[0][1]);
                        MMAH(oc[u][1], a0, a1, a2, a3, cur[0][2], cur[0][3]);
                        MMAH(oc[u][2], a0, a1, a2, a3, cur[1][0], cur[1][1]);
                        MMAH(oc[u][3], a0, a1, a2, a3, cur[1][2], cur[1][3]);
                    }
                    if (ks == 0) {
#pragma unroll
                        for (int m2 = 0; m2 < 2; m2++)
#pragma unroll
                            for (int e = 0; e < 4; e++) cur[m2][e] = nxt[m2][e];
                    }
                }
            }

            __syncthreads();
            if (j + 2 < n) loadKV(c0 + j + 2, b);
            CP_COMMIT();
        }

        // ---------- epilogue: transpose O^T -> O via smem (256 rows), write slot ----------
        CP_WAIT(0);
        __syncthreads();
        const int slot = 2 * ci + seg;
        {
            const int dq = lane >> 2;
            const int mq = 2 * (lane & 3);
#pragma unroll
            for (int u = 0; u < 8; u++) {
#pragma unroll
                for (int nb = 0; nb < 4; nb++) {
                    int d0 = 16 * u + dq;
                    int m0 = w * 32 + 8 * nb + mq;
#pragma unroll
                    for (int e = 0; e < 4; e++) {
                        int d = d0 + (e >> 1) * 8;
                        int m = m0 + (e & 1);
                        uint32_t adr = base + m * 512 +
                                       (uint32_t)((((d >> 2) ^ (m & 7)) << 4) + (d & 3) * 4);
                        asm volatile("st.shared.b32 [%0], %1;" :: "r"(adr), "f"(oc[u][nb][e]) : "memory");
                    }
                }
            }
        }
        __syncthreads();
        {
            int m = tid;     // 0..255
            float* gO = &g_Opart[(size_t)slot * 32768 + (size_t)m * 128];
#pragma unroll
            for (int ch = 0; ch < 32; ch++) {
                uint32_t adr = base + m * 512 + (uint32_t)((ch ^ (m & 7)) << 4);
                float4 v;
                asm volatile("ld.shared.v4.f32 {%0,%1,%2,%3}, [%4];"
                             : "=f"(v.x), "=f"(v.y), "=f"(v.z), "=f"(v.w) : "r"(adr));
                *reinterpret_cast<float4*>(gO + ch * 4) = v;
            }
        }
#pragma unroll
        for (int jj = 0; jj < 4; jj++) {
            rs[jj] += __shfl_xor_sync(0xffffffffu, rs[jj], 1);
            rs[jj] += __shfl_xor_sync(0xffffffffu, rs[jj], 2);
        }
        if ((lane & 3) == 0) {
#pragma unroll
            for (int jj = 0; jj < 4; jj++) {
                int m = w * 32 + 8 * jj + (lane >> 2);
                g_Rpart[slot * 256 + m] = rs[jj];
            }
        }
        __syncthreads();     // before next segment reuses smem

        g = segend;
        seg++;
    }
}

// ============================================================
// combine: sum covering CTA partials and normalize
// ============================================================
__global__ void __launch_bounds__(128)
kvmem_combine(float* __restrict__ out) {
    int rowg = blockIdx.x;               // 0..8191
    int hm = rowg >> 7, m = rowg & 127;
    int head = hm >> 3, mt = hm & 7;
    int hm2 = head * 4 + (mt >> 1);
    int mrow = (mt & 1) * 128 + m;       // row within 256-row partial
    int d = threadIdx.x;

    int gfirst = hm2 << 8, glast = gfirst + 255;
    int i = gfirst / 55;
    if (i > NCTA - 1) i = NCTA - 1;
    while (i > 0 && cta_start2(i) > gfirst) i--;
    while (cta_start2(i) + cta_len2(i) <= gfirst) i++;

    float acc = 0.f, rsum = 0.f;
    for (; i < NCTA && cta_start2(i) <= glast; i++) {
        int segidx = ((cta_start2(i) >> 8) == hm2) ? 0 : 1;
        int slot = 2 * i + segidx;
        acc  += g_Opart[(size_t)slot * 32768 + (size_t)mrow * 128 + d];
        rsum += g_Rpart[slot * 256 + mrow];
    }
    out[(size_t)(mt * 128 + m) * MEMDIM + head * 128 + d] = acc / rsum;
}

extern "C" void kernel_launch(void* const* d_in, const int* in_sizes, int n_in,
                              void* d_out, int out_size) {
    const float* hin    = (const float*)d_in[0];
    const float* keys   = (const float*)d_in[1];
    const float* values = (const float*)d_in[2];
    float* out = (float*)d_out;
    kvmem_prepass<<<1184, 256>>>(hin, keys, values);
    cudaFuncSetAttribute(kvmem_main, cudaFuncAttributeMaxDynamicSharedMemorySize, SMEM_BYTES);
    kvmem_main<<<NCTA, 256, SMEM_BYTES>>>();
    kvmem_combine<<<8192, 128>>>(out);
}

// round 17
// speedup vs baseline: 1.0887x; 1.0887x over previous
#include <cuda_runtime.h>
#include <cuda_fp16.h>
#include <cstdint>
#include <cstddef>

#define NHEADS   8
#define MEMDIM   1024
#define MEMSIZE  32768
#define TZ       128
#define NCTA     148

// smem layout (fp16 tiles): K/V = 128 rows x 256B each
#define OFF_K0   0u
#define OFF_K1   32768u
#define OFF_V0   65536u
#define OFF_V1   98304u
#define OFF_Q    131072u
#define SMEM_BYTES (131072u + 32768u)   // 160 KB

// fp16 copies of the inputs (filled by prepass each launch)
// g_Qh holds Q pre-scaled by log2(e) so exp(S) = ex2(S')
__device__ __half g_Qh[1024 * 1024];
__device__ __half g_Kh[(size_t)MEMSIZE * MEMDIM];
__device__ __half g_Vh[(size_t)MEMDIM * MEMSIZE];

// per-(CTA,segment) partial outputs (deterministic, no atomics)
__device__ float g_Opart[(size_t)2 * NCTA * 128 * 128];
__device__ float g_Rpart[2 * NCTA * 128];

// static partition: 16384 = 104*111 + 44*110
__host__ __device__ __forceinline__ int cta_start(int i) {
    return i * 110 + (i < 104 ? i : 104);
}
__host__ __device__ __forceinline__ int cta_len(int i) {
    return 110 + (i < 104 ? 1 : 0);
}

// ---------------- helpers ----------------
__device__ __forceinline__ uint32_t smem_u32(const void* p) {
    uint32_t a;
    asm("{ .reg .u64 t; cvta.to.shared.u64 t, %1; cvt.u32.u64 %0, t; }" : "=r"(a) : "l"(p));
    return a;
}

#define CP16(dst, src) \
    asm volatile("cp.async.cg.shared.global [%0], [%1], 16;" :: "r"(dst), "l"(src) : "memory")
#define CP_COMMIT() asm volatile("cp.async.commit_group;" ::: "memory")
#define CP_WAIT(n)  asm volatile("cp.async.wait_group %0;" :: "n"(n) : "memory")

#define LDSM4(r0, r1, r2, r3, a) \
    asm volatile("ldmatrix.sync.aligned.m8n8.x4.shared.b16 {%0,%1,%2,%3}, [%4];" \
        : "=r"(r0), "=r"(r1), "=r"(r2), "=r"(r3) : "r"(a))

#define MMAH(c, a0, a1, a2, a3, b0, b1) \
    asm volatile("mma.sync.aligned.m16n8k16.row.col.f32.f16.f16.f32 " \
        "{%0,%1,%2,%3}, {%4,%5,%6,%7}, {%8,%9}, {%0,%1,%2,%3};" \
        : "+f"((c)[0]), "+f"((c)[1]), "+f"((c)[2]), "+f"((c)[3]) \
        : "r"(a0), "r"(a1), "r"(a2), "r"(a3), "r"(b0), "r"(b1))

__device__ __forceinline__ uint32_t packh2(float lo, float hi) {
    __half2 h = __floats2half2_rn(lo, hi);
    return *reinterpret_cast<uint32_t*>(&h);
}

// exp2 of a packed f16x2 (one MUFU op for two values)
__device__ __forceinline__ uint32_t ex2h2(uint32_t p) {
    uint32_t r;
    asm("ex2.approx.f16x2 %0, %1;" : "=r"(r) : "r"(p));
    return r;
}

// exp (base-2, inputs pre-scaled) of one 4-reg score block -> two half2 frags.
__device__ __forceinline__ void exp_block(const float* s, uint32_t& lo, uint32_t& hi,
                                          float& r0, float& r1) {
    lo = ex2h2(packh2(s[0], s[1]));
    hi = ex2h2(packh2(s[2], s[3]));
    float2 el = __half22float2(*reinterpret_cast<const __half2*>(&lo));
    float2 eh = __half22float2(*reinterpret_cast<const __half2*>(&hi));
    r0 += el.x + el.y;
    r1 += eh.x + eh.y;
}

// ============================================================
// prepass: f32 -> fp16 copies; Q scaled by log2(e)
// ============================================================
__global__ void __launch_bounds__(256)
kvmem_prepass(const float* __restrict__ hin, const float* __restrict__ keys,
              const float* __restrict__ values) {
    const size_t NQ4 = (size_t)1024 * 1024 / 4;
    const size_t NK4 = (size_t)MEMSIZE * MEMDIM / 4;
    const size_t NV4 = NK4;
    const size_t TOT = NQ4 + NK4 + NV4;
    const float LOG2E = 1.4426950408889634f;
    size_t stride = (size_t)gridDim.x * blockDim.x;
    for (size_t i = (size_t)blockIdx.x * blockDim.x + threadIdx.x; i < TOT; i += stride) {
        const float4* src;
        uint2* dst;
        size_t off;
        float scale;
        if (i < NQ4) {
            src = (const float4*)hin; dst = (uint2*)g_Qh; off = i; scale = LOG2E;
        } else if (i < NQ4 + NK4) {
            src = (const float4*)keys; dst = (uint2*)g_Kh; off = i - NQ4; scale = 1.0f;
        } else {
            src = (const float4*)values; dst = (uint2*)g_Vh; off = i - NQ4 - NK4; scale = 1.0f;
        }
        float4 v = src[off];
        uint2 u;
        u.x = packh2(v.x * scale, v.y * scale);
        u.y = packh2(v.z * scale, v.w * scale);
        dst[off] = u;
    }
}

// ============================================================
// main kernel: 148 CTAs, static contiguous chunk ranges
// ============================================================
__global__ void __launch_bounds__(256, 1)
kvmem_main() {
    extern __shared__ __align__(1024) char dsm[];
    const uint32_t base = smem_u32(dsm);

    const int tid  = threadIdx.x;
    const int lane = tid & 31;
    const int w    = tid >> 5;
    const int ci   = blockIdx.x;

    const int rstart = cta_start(ci);
    const int rend   = rstart + cta_len(ci);

    const uint32_t Kb[2] = { base + OFF_K0, base + OFF_K1 };
    const uint32_t Vb[2] = { base + OFF_V0, base + OFF_V1 };
    const uint32_t Qs    = base + OFF_Q;

    // per-thread precomputed load offsets (K/V tiles: 128 rows x 16 chunks)
    uint32_t tdoff[8], ksoff[8], vsoff[8];
#pragma unroll
    for (int n = 0; n < 8; n++) {
        int c = tid + 256 * n;
        int r = c >> 4, ch = c & 15;
        tdoff[n] = (uint32_t)(r * 256 + ((ch ^ (r & 7)) << 4));
        ksoff[n] = (uint32_t)(((size_t)r * MEMDIM + ch * 8) * 2);
        vsoff[n] = (uint32_t)(((size_t)r * MEMSIZE + ch * 8) * 2);
    }

    // lane addressing constants
    const int krow_off = ((lane >> 4) << 3) + (lane & 7);
    const int kch_off  = (lane >> 3) & 1;
    const int vrow_off = ((lane >> 3) & 1) * 8 + (lane & 7);
    const int vch_off  = lane >> 4;

    int seg = 0;
    int g = rstart;
    while (g < rend) {
        const int hm   = g >> 8;
        const int segend = min(rend, (hm + 1) << 8);
        const int n    = segend - g;
        const int c0   = g & 255;
        const int head = hm >> 3, mt = hm & 7;

        const char* kptr = (const char*)(g_Kh + head * 128);
        const char* vptr = (const char*)(g_Vh + (size_t)(head * 128) * MEMSIZE);

        auto loadKV = [&](int c, int b) {   // c = absolute chunk 0..255
            const char* ks = kptr + (size_t)c * (TZ * MEMDIM * 2);
            const char* vs = vptr + (size_t)c * (TZ * 2);
#pragma unroll
            for (int q = 0; q < 8; q++) CP16(Kb[b] + tdoff[q], ks + ksoff[q]);
#pragma unroll
            for (int q = 0; q < 8; q++) CP16(Vb[b] + tdoff[q], vs + vsoff[q]);
        };

        // ---------- stage Q (128 rows x 256B, swizzled) ----------
        {
            const __half* qsrc = g_Qh + (size_t)(mt * 128) * MEMDIM + head * 128;
#pragma unroll
            for (int c = tid; c < 2048; c += 256) {
                int m = c >> 4, ch = c & 15;
                uint32_t dst = Qs + m * 256 + (uint32_t)((ch ^ (m & 7)) << 4);
                CP16(dst, qsrc + (size_t)m * MEMDIM + ch * 8);
            }
            CP_COMMIT();
        }
        loadKV(c0, 0); CP_COMMIT();
        if (n > 1) loadKV(c0 + 1, 1);
        CP_COMMIT();

        // ---------- Q a-frags ----------
        uint32_t qa[8][4];
        CP_WAIT(2);
        __syncthreads();
        {
            const int row = w * 16 + ((lane >> 3) & 1) * 8 + (lane & 7);
            const int cb  = lane >> 4;
#pragma unroll
            for (int s = 0; s < 8; s++) {
                int ch = 2 * s + cb;
                uint32_t a = Qs + row * 256 + (uint32_t)((ch ^ (row & 7)) << 4);
                LDSM4(qa[s][0], qa[s][1], qa[s][2], qa[s][3], a);
            }
        }

        float oc[8][2][4];
#pragma unroll
        for (int u = 0; u < 8; u++)
#pragma unroll
            for (int h = 0; h < 2; h++) { oc[u][h][0] = oc[u][h][1] = oc[u][h][2] = oc[u][h][3] = 0.f; }
        float rs0 = 0.f, rs1 = 0.f;

#pragma unroll 1
        for (int j = 0; j < n; j++) {
            const int b = j & 1;
            CP_WAIT(1);
            __syncthreads();
            const uint32_t kb = Kb[b], vb = Vb[b];

#pragma unroll
            for (int sub = 0; sub < 2; sub++) {
                // ---------- GEMM1 with exp interleaved per jp-group ----------
                // After jp-group's MMAs, its two score blocks are final; their
                // exp (MUFU) issues while the next jp-group's MMAs occupy the
                // tensor pipe. GEMM2 then has all P frags ready (no serial MUFU).
                float sc[8][4];
#pragma unroll
                for (int jj = 0; jj < 8; jj++) { sc[jj][0] = sc[jj][1] = sc[jj][2] = sc[jj][3] = 0.f; }
                uint32_t pl[8], ph[8];
#pragma unroll
                for (int jp = 0; jp < 4; jp++) {
#pragma unroll
                    for (int s = 0; s < 8; s++) {
                        int row = sub * 64 + 16 * jp + krow_off;
                        int ch  = 2 * s + kch_off;
                        uint32_t a = kb + row * 256 + (uint32_t)((ch ^ (row & 7)) << 4);
                        uint32_t r0, r1, r2, r3;
                        LDSM4(r0, r1, r2, r3, a);
                        MMAH(sc[2 * jp],     qa[s][0], qa[s][1], qa[s][2], qa[s][3], r0, r1);
                        MMAH(sc[2 * jp + 1], qa[s][0], qa[s][1], qa[s][2], qa[s][3], r2, r3);
                    }
                    exp_block(sc[2 * jp],     pl[2 * jp],     ph[2 * jp],     rs0, rs1);
                    exp_block(sc[2 * jp + 1], pl[2 * jp + 1], ph[2 * jp + 1], rs0, rs1);
                }

                // ---------- GEMM2: pure LDSM + MMA ----------
#pragma unroll
                for (int s2 = 0; s2 < 4; s2++) {
#pragma unroll
                    for (int u = 0; u < 8; u++) {
                        int row = 16 * u + vrow_off;
                        int ch  = sub * 8 + 2 * s2 + vch_off;
                        uint32_t a = vb + row * 256 + (uint32_t)((ch ^ (row & 7)) << 4);
                        uint32_t a0, a1, a2, a3;
                        LDSM4(a0, a1, a2, a3, a);
                        MMAH(oc[u][0], a0, a1, a2, a3, pl[2 * s2], pl[2 * s2 + 1]);
                        MMAH(oc[u][1], a0, a1, a2, a3, ph[2 * s2], ph[2 * s2 + 1]);
                    }
                }
            }

            __syncthreads();
            if (j + 2 < n) loadKV(c0 + j + 2, b);
            CP_COMMIT();
        }

        // ---------- epilogue: transpose O^T -> O via smem, write partial slot ----------
        CP_WAIT(0);
        __syncthreads();
        const int slot = 2 * ci + seg;
        {
            const int dq = lane >> 2;
            const int mq = 2 * (lane & 3);
#pragma unroll
            for (int u = 0; u < 8; u++) {
#pragma unroll
                for (int h = 0; h < 2; h++) {
                    int d0 = 16 * u + dq;
                    int m0 = w * 16 + 8 * h + mq;
#pragma unroll
                    for (int e = 0; e < 4; e++) {
                        int d = d0 + (e >> 1) * 8;
                        int m = m0 + (e & 1);
                        uint32_t adr = base + m * 512 +
                                       (uint32_t)((((d >> 2) ^ (m & 7)) << 4) + (d & 3) * 4);
                        asm volatile("st.shared.b32 [%0], %1;" :: "r"(adr), "f"(oc[u][h][e]) : "memory");
                    }
                }
            }
        }
        __syncthreads();
        {
            int m = tid >> 1, half = tid & 1;
            float* gO = &g_Opart[(size_t)slot * 16384 + (size_t)m * 128];
#pragma unroll
            for (int c = 0; c < 16; c++) {
                int ch = half * 16 + c;
                uint32_t adr = base + m * 512 + (uint32_t)((ch ^ (m & 7)) << 4);
                float4 v;
                asm volatile("ld.shared.v4.f32 {%0,%1,%2,%3}, [%4];"
                             : "=f"(v.x), "=f"(v.y), "=f"(v.z), "=f"(v.w) : "r"(adr));
                *reinterpret_cast<float4*>(gO + ch * 4) = v;
            }
        }
        rs0 += __shfl_xor_sync(0xffffffffu, rs0, 1);
        rs0 += __shfl_xor_sync(0xffffffffu, rs0, 2);
        rs1 += __shfl_xor_sync(0xffffffffu, rs1, 1);
        rs1 += __shfl_xor_sync(0xffffffffu, rs1, 2);
        if ((lane & 3) == 0) {
            int r0 = w * 16 + (lane >> 2);
            g_Rpart[slot * 128 + r0]     = rs0;
            g_Rpart[slot * 128 + r0 + 8] = rs1;
        }
        __syncthreads();     // before next segment's cp.async reuses smem

        g = segend;
        seg++;
    }
}

// ============================================================
// combine: sum covering CTA partials and normalize
// ============================================================
__global__ void __launch_bounds__(128)
kvmem_combine(float* __restrict__ out) {
    int rowg = blockIdx.x;               // 0..8191
    int hm = rowg >> 7, m = rowg & 127;
    int head = hm >> 3, mt = hm & 7;
    int d = threadIdx.x;

    int gfirst = hm << 8, glast = gfirst + 255;
    int i = gfirst / 110;
    if (i > NCTA - 1) i = NCTA - 1;
    while (i > 0 && cta_start(i) > gfirst) i--;
    while (cta_start(i) + cta_len(i) <= gfirst) i++;

    float acc = 0.f, rs = 0.f;
    for (; i < NCTA && cta_start(i) <= glast; i++) {
        int segidx = ((cta_start(i) >> 8) == hm) ? 0 : 1;
        int slot = 2 * i + segidx;
        acc += g_Opart[(size_t)slot * 16384 + (size_t)m * 128 + d];
        rs  += g_Rpart[slot * 128 + m];
    }
    out[(size_t)(mt * 128 + m) * MEMDIM + head * 128 + d] = acc / rs;
}

extern "C" void kernel_launch(void* const* d_in, const int* in_sizes, int n_in,
                              void* d_out, int out_size) {
    const float* hin    = (const float*)d_in[0];
    const float* keys   = (const float*)d_in[1];
    const float* values = (const float*)d_in[2];
    float* out = (float*)d_out;
    kvmem_prepass<<<1184, 256>>>(hin, keys, values);
    cudaFuncSetAttribute(kvmem_main, cudaFuncAttributeMaxDynamicSharedMemorySize, SMEM_BYTES);
    kvmem_main<<<NCTA, 256, SMEM_BYTES>>>();
    kvmem_combine<<<8192, 128>>>(out);
}